// round 2
// baseline (speedup 1.0000x reference)
#include <cuda_runtime.h>
#include <cuda_bf16.h>
#include <math.h>

// Problem constants (fixed by setup_inputs)
#define Nn   32000
#define Hh   128
#define Ll   3
#define Rr   8
#define Ee   512000
#define BSz  32
#define Kk   64
#define NPG  1000

// Scratch (device globals; no runtime allocation allowed)
__device__ float g_agg[(size_t)Nn * Rr * Hh];     // 131 MB
__device__ float g_repr[(size_t)Ll * Nn * Hh];    // 49 MB, layer-major [L,N,H]
__device__ float g_mean_buf[BSz * Ll * Hh];       // [b, l, i]

// ---------------------------------------------------------------------------
// Zero the aggregation buffer (float4 grid-stride-free exact launch)
// ---------------------------------------------------------------------------
__global__ void zero_agg_kernel() {
    size_t i = (size_t)blockIdx.x * blockDim.x + threadIdx.x;
    float4 z = make_float4(0.f, 0.f, 0.f, 0.f);
    ((float4*)g_agg)[i] = z;   // launched with exactly N*R*H/4 threads
}

// ---------------------------------------------------------------------------
// Edge scatter: one warp per edge, red.global.add.v4.f32 into agg[(dst*R+et)*H]
// ---------------------------------------------------------------------------
__global__ void scatter_kernel(const float* __restrict__ h,
                               const int* __restrict__ src,
                               const int* __restrict__ dst,
                               const int* __restrict__ et) {
    int w = (int)(((size_t)blockIdx.x * blockDim.x + threadIdx.x) >> 5);
    int lane = threadIdx.x & 31;
    if (w >= Ee) return;
    int s = src[w], d = dst[w], r = et[w];
    float4 v = *(const float4*)(h + (size_t)s * Hh + lane * 4);
    float* p = g_agg + ((size_t)d * Rr + r) * Hh + lane * 4;
    asm volatile("red.global.add.v4.f32 [%0], {%1,%2,%3,%4};"
                 :: "l"(p), "f"(v.x), "f"(v.y), "f"(v.z), "f"(v.w) : "memory");
}

// ---------------------------------------------------------------------------
// Fused RGCN GEMM: out = relu( [agg | h_in] @ [W_rel_l ; W_self_l] )
// M=32000, Nout=128, K=1152. BM=128, BN=128, BK=16, 256 thr, 8x8/thread,
// double-buffered smem (one sync per K-tile).
// ---------------------------------------------------------------------------
#define BK 16
#define NTILES ((Rr * Hh + Hh) / BK)   // 72

__global__ __launch_bounds__(256, 2)
void rgcn_gemm_kernel(const float* __restrict__ h_in,      // [N,128]
                      const float* __restrict__ W_rel_l,   // [1024,128]
                      const float* __restrict__ W_self_l,  // [128,128]
                      float* __restrict__ out)             // [N,128]
{
    __shared__ float As[2][BK][128];
    __shared__ float Bs[2][BK][128];

    const int tid  = threadIdx.x;
    const int row0 = blockIdx.x * 128;
    const int tx   = tid & 15;   // col group (8 cols)
    const int ty   = tid >> 4;   // row group (8 rows)

    float acc[8][8];
    #pragma unroll
    for (int i = 0; i < 8; i++)
        #pragma unroll
        for (int j = 0; j < 8; j++) acc[i][j] = 0.f;

    float4 aR[2], bR[2];

    auto gload = [&](int t) {
        int k0 = t * BK;
        #pragma unroll
        for (int i = 0; i < 2; i++) {
            int idx = tid + i * 256;
            int ar = idx >> 2, ac = (idx & 3) * 4;
            int gk = k0 + ac;
            const float* ap = (gk < Rr * Hh)
                ? (g_agg + (size_t)(row0 + ar) * (Rr * Hh) + gk)
                : (h_in + (size_t)(row0 + ar) * Hh + (gk - Rr * Hh));
            aR[i] = *(const float4*)ap;
            int br = idx >> 5, bc = (idx & 31) * 4;
            int gkb = k0 + br;
            const float* bp = (gkb < Rr * Hh)
                ? (W_rel_l + (size_t)gkb * Hh + bc)
                : (W_self_l + (size_t)(gkb - Rr * Hh) * Hh + bc);
            bR[i] = *(const float4*)bp;
        }
    };
    auto sstore = [&](int buf) {
        #pragma unroll
        for (int i = 0; i < 2; i++) {
            int idx = tid + i * 256;
            int ar = idx >> 2, ac = (idx & 3) * 4;
            As[buf][ac + 0][ar] = aR[i].x;
            As[buf][ac + 1][ar] = aR[i].y;
            As[buf][ac + 2][ar] = aR[i].z;
            As[buf][ac + 3][ar] = aR[i].w;
            int br = idx >> 5, bc = (idx & 31) * 4;
            *(float4*)&Bs[buf][br][bc] = bR[i];
        }
    };

    gload(0); sstore(0); __syncthreads();

    for (int t = 0; t < NTILES; t++) {
        int cur = t & 1;
        if (t + 1 < NTILES) gload(t + 1);
        #pragma unroll
        for (int k = 0; k < BK; k++) {
            float4 a0 = *(float4*)&As[cur][k][ty * 8];
            float4 a1 = *(float4*)&As[cur][k][ty * 8 + 4];
            float4 b0 = *(float4*)&Bs[cur][k][tx * 8];
            float4 b1 = *(float4*)&Bs[cur][k][tx * 8 + 4];
            float av[8] = {a0.x, a0.y, a0.z, a0.w, a1.x, a1.y, a1.z, a1.w};
            float bv[8] = {b0.x, b0.y, b0.z, b0.w, b1.x, b1.y, b1.z, b1.w};
            #pragma unroll
            for (int i = 0; i < 8; i++)
                #pragma unroll
                for (int j = 0; j < 8; j++)
                    acc[i][j] = fmaf(av[i], bv[j], acc[i][j]);
        }
        if (t + 1 < NTILES) { sstore((t + 1) & 1); __syncthreads(); }
    }

    // epilogue: relu + store
    #pragma unroll
    for (int i = 0; i < 8; i++) {
        int row = row0 + ty * 8 + i;
        float* op = out + (size_t)row * Hh + tx * 8;
        float4 o0, o1;
        o0.x = fmaxf(acc[i][0], 0.f); o0.y = fmaxf(acc[i][1], 0.f);
        o0.z = fmaxf(acc[i][2], 0.f); o0.w = fmaxf(acc[i][3], 0.f);
        o1.x = fmaxf(acc[i][4], 0.f); o1.y = fmaxf(acc[i][5], 0.f);
        o1.z = fmaxf(acc[i][6], 0.f); o1.w = fmaxf(acc[i][7], 0.f);
        *(float4*)op = o0;
        *(float4*)(op + 4) = o1;
    }
}

// ---------------------------------------------------------------------------
// Mean pooling per (graph, layer). Graphs are contiguous [b*NPG, (b+1)*NPG).
// ---------------------------------------------------------------------------
__global__ void pool_kernel() {
    int b = blockIdx.x / Ll, l = blockIdx.x % Ll, i = threadIdx.x;
    const float* p = g_repr + (size_t)l * Nn * Hh + (size_t)b * NPG * Hh + i;
    float s = 0.f;
    for (int n = 0; n < NPG; n++) s += p[(size_t)n * Hh];
    g_mean_buf[(b * Ll + l) * Hh + i] = s * (1.0f / NPG);
}

// ---------------------------------------------------------------------------
// Fused final head: one block per batch element, 128 threads.
// ---------------------------------------------------------------------------
__global__ void final_kernel(const float* __restrict__ rel_table,
                             const float* __restrict__ Zn,
                             const float* __restrict__ proj_W,
                             const float* __restrict__ proj_b,
                             const float* __restrict__ fc_W,
                             const float* __restrict__ fc_b,
                             const float* __restrict__ rep_seq,
                             const int* __restrict__ head_ids,
                             const int* __restrict__ tail_ids,
                             const int* __restrict__ rel_labels,
                             float* __restrict__ out)
{
    int b = blockIdx.x, i = threadIdx.x;
    __shared__ float sh_head[Ll * Hh], sh_tail[Ll * Hh], sh_gm[Ll * Hh];
    __shared__ float sh_gout[Hh], sh_hout[Hh], sh_tout[Hh];
    __shared__ float sh_e1[Kk], sh_e2[Kk];
    __shared__ float red[Hh];

    int head = head_ids[b], tail = tail_ids[b], rl = rel_labels[b];

    for (int j = i; j < Ll * Hh; j += Hh) {
        int l = j >> 7, c = j & 127;
        sh_head[j] = g_repr[(size_t)l * Nn * Hh + (size_t)head * Hh + c];
        sh_tail[j] = g_repr[(size_t)l * Nn * Hh + (size_t)tail * Hh + c];
        sh_gm[j]   = g_mean_buf[(b * Ll + l) * Hh + c];
    }
    __syncthreads();

    // three [384]@[384x128] proj matvecs
    float bias = proj_b[i];
    float ag = bias, ah = bias, at = bias;
    for (int j = 0; j < Ll * Hh; j++) {
        float w = proj_W[j * Hh + i];
        ag = fmaf(sh_gm[j],   w, ag);
        ah = fmaf(sh_head[j], w, ah);
        at = fmaf(sh_tail[j], w, at);
    }
    sh_gout[i] = (ag >= 0.f) ? ag : 0.01f * ag;   // leaky_relu
    sh_hout[i] = ah;
    sh_tout[i] = at;
    __syncthreads();

    // community logits: k < 64 threads compute dots with Zn rows
    float lg1 = 0.f, lg2 = 0.f;
    if (i < Kk) {
        const float* z = Zn + (size_t)i * Hh;
        for (int c = 0; c < Hh; c++) {
            lg1 = fmaf(sh_hout[c], z[c], lg1);
            lg2 = fmaf(sh_tout[c], z[c], lg2);
        }
        sh_e1[i] = lg1; sh_e2[i] = lg2;
    }
    __syncthreads();
    float m1 = -1e30f, m2 = -1e30f;
    for (int k = 0; k < Kk; k++) {
        m1 = fmaxf(m1, sh_e1[k]);
        m2 = fmaxf(m2, sh_e2[k]);
    }
    __syncthreads();
    if (i < Kk) { sh_e1[i] = expf(lg1 - m1); sh_e2[i] = expf(lg2 - m2); }
    __syncthreads();
    float sum1 = 0.f, sum2 = 0.f;
    for (int k = 0; k < Kk; k++) { sum1 += sh_e1[k]; sum2 += sh_e2[k]; }
    float a1 = 0.f, a2 = 0.f;
    for (int k = 0; k < Kk; k++) {
        float zi = Zn[(size_t)k * Hh + i];
        a1 = fmaf(sh_e1[k], zi, a1);
        a2 = fmaf(sh_e2[k], zi, a2);
    }
    a1 /= sum1; a2 /= sum2;
    float sview = (1.f / (1.f + expf(-a1))) * (1.f / (1.f + expf(-a2)));

    // view attention
    float relv = rel_table[(size_t)rl * Hh + i];
    float v0 = sh_gout[i];
    float v1 = rep_seq[(size_t)b * Hh + i];
    float v2 = sview;

    float d[3];
    float parts[3] = {relv * v0, relv * v1, relv * v2};
    #pragma unroll
    for (int v = 0; v < 3; v++) {
        red[i] = parts[v];
        __syncthreads();
        for (int s = 64; s > 0; s >>= 1) {
            if (i < s) red[i] += red[i + s];
            __syncthreads();
        }
        d[v] = red[0];
        __syncthreads();
    }
    float dm = fmaxf(d[0], fmaxf(d[1], d[2]));
    float e0 = expf(d[0] - dm), e1 = expf(d[1] - dm), e2 = expf(d[2] - dm);
    float es = e0 + e1 + e2;
    float att0 = e0 / es, att1 = e1 / es, att2 = e2 / es;
    float vag = att0 * v0 + att1 * v1 + att2 * v2;

    // final dot with fc_W [1024]
    float part = 0.f;
    #pragma unroll
    for (int l = 0; l < Ll; l++) {
        part = fmaf(sh_head[l * Hh + i], fc_W[l * Hh + i], part);
        part = fmaf(sh_tail[l * Hh + i], fc_W[Ll * Hh + l * Hh + i], part);
    }
    part = fmaf(relv, fc_W[2 * Ll * Hh + i], part);
    part = fmaf(vag,  fc_W[2 * Ll * Hh + Hh + i], part);
    red[i] = part;
    __syncthreads();
    for (int s = 64; s > 0; s >>= 1) {
        if (i < s) red[i] += red[i + s];
        __syncthreads();
    }
    if (i == 0) out[b] = red[0] + fc_b[0];
}

// ---------------------------------------------------------------------------
extern "C" void kernel_launch(void* const* d_in, const int* in_sizes, int n_in,
                              void* d_out, int out_size) {
    const float* x         = (const float*)d_in[0];
    const float* W_rel     = (const float*)d_in[1];
    const float* W_self    = (const float*)d_in[2];
    const float* rel_table = (const float*)d_in[3];
    const float* Zn        = (const float*)d_in[4];
    const float* proj_W    = (const float*)d_in[5];
    const float* proj_b    = (const float*)d_in[6];
    const float* fc_W      = (const float*)d_in[7];
    const float* fc_b      = (const float*)d_in[8];
    const float* rep_seq   = (const float*)d_in[9];
    const int*   src       = (const int*)d_in[10];
    const int*   dst       = (const int*)d_in[11];
    const int*   etype     = (const int*)d_in[12];
    // d_in[13] = graph_id (contiguous blocks, unused)
    const int*   head_ids  = (const int*)d_in[14];
    const int*   tail_ids  = (const int*)d_in[15];
    const int*   rel_labels= (const int*)d_in[16];
    float* out = (float*)d_out;

    float* repr_base;
    cudaGetSymbolAddress((void**)&repr_base, g_repr);

    const int zero_threads = 256;
    const int zero_blocks  = (Nn * Rr * Hh / 4) / zero_threads;   // exact
    const int scat_blocks  = (Ee * 32) / 256;                     // one warp/edge
    const int gemm_blocks  = Nn / 128;                            // 250

    for (int l = 0; l < Ll; l++) {
        const float* h_in = (l == 0) ? x : (repr_base + (size_t)(l - 1) * Nn * Hh);
        float* h_out = repr_base + (size_t)l * Nn * Hh;
        zero_agg_kernel<<<zero_blocks, zero_threads>>>();
        scatter_kernel<<<scat_blocks, 256>>>(h_in, src, dst, etype);
        rgcn_gemm_kernel<<<gemm_blocks, 256>>>(h_in,
                                               W_rel + (size_t)l * Rr * Hh * Hh,
                                               W_self + (size_t)l * Hh * Hh,
                                               h_out);
    }
    pool_kernel<<<BSz * Ll, Hh>>>();
    final_kernel<<<BSz, Hh>>>(rel_table, Zn, proj_W, proj_b, fc_W, fc_b,
                              rep_seq, head_ids, tail_ids, rel_labels, out);
}

// round 5
// speedup vs baseline: 1.7740x; 1.7740x over previous
#include <cuda_runtime.h>
#include <cuda_bf16.h>
#include <math.h>
#include <cstdint>

// Problem constants (fixed by setup_inputs)
#define Nn   32000
#define Hh   128
#define Ll   3
#define Rr   8
#define Ee   512000
#define BSz  32
#define Kk   64
#define NPG  1000
#define KK   1152   // R*H + H

// Scratch (device globals; no runtime allocation allowed)
__device__ float g_agg[(size_t)Nn * Rr * Hh];     // 131 MB
__device__ float g_repr[(size_t)Ll * Nn * Hh];    // 49 MB, layer-major [L,N,H]
__device__ float g_mean_buf[BSz * Ll * Hh];       // [b, l, i]
// Pre-converted weights, bf16 hi/lo split, [L][n=128][k=1152] (B = W^T, K-major)
__device__ __nv_bfloat16 g_Whi[(size_t)Ll * Hh * KK];
__device__ __nv_bfloat16 g_Wlo[(size_t)Ll * Hh * KK];

__device__ __forceinline__ uint32_t smem_to_u32(const void* smem_ptr) {
    uint32_t addr;
    asm("{ .reg .u64 tmp; cvta.to.shared.u64 tmp, %1; cvt.u32.u64 %0, tmp; }"
        : "=r"(addr) : "l"(smem_ptr));
    return addr;
}

// ---------------------------------------------------------------------------
// Zero the aggregation buffer
// ---------------------------------------------------------------------------
__global__ void zero_agg_kernel() {
    size_t i = (size_t)blockIdx.x * blockDim.x + threadIdx.x;
    float4 z = make_float4(0.f, 0.f, 0.f, 0.f);
    ((float4*)g_agg)[i] = z;
}

// ---------------------------------------------------------------------------
// Edge scatter: one warp per edge, red.global.add.v4.f32
// ---------------------------------------------------------------------------
__global__ void scatter_kernel(const float* __restrict__ h,
                               const int* __restrict__ src,
                               const int* __restrict__ dst,
                               const int* __restrict__ et) {
    int w = (int)(((size_t)blockIdx.x * blockDim.x + threadIdx.x) >> 5);
    int lane = threadIdx.x & 31;
    if (w >= Ee) return;
    int s = src[w], d = dst[w], r = et[w];
    float4 v = *(const float4*)(h + (size_t)s * Hh + lane * 4);
    float* p = g_agg + ((size_t)d * Rr + r) * Hh + lane * 4;
    asm volatile("red.global.add.v4.f32 [%0], {%1,%2,%3,%4};"
                 :: "l"(p), "f"(v.x), "f"(v.y), "f"(v.z), "f"(v.w) : "memory");
}

// ---------------------------------------------------------------------------
// Weight pre-conversion: B[l][n][k] = W[k][n], bf16 hi/lo split
// ---------------------------------------------------------------------------
__global__ void conv_w_kernel(const float* __restrict__ W_rel,
                              const float* __restrict__ W_self) {
    size_t idx = (size_t)blockIdx.x * blockDim.x + threadIdx.x;
    if (idx >= (size_t)Ll * Hh * KK) return;
    int k = (int)(idx % KK);
    int n = (int)((idx / KK) % Hh);
    int l = (int)(idx / ((size_t)KK * Hh));
    float w = (k < Rr * Hh)
        ? W_rel[((size_t)l * Rr * Hh + k) * Hh + n]
        : W_self[((size_t)l * Hh + (k - Rr * Hh)) * Hh + n];
    __nv_bfloat16 hi = __float2bfloat16(w);
    __nv_bfloat16 lo = __float2bfloat16(w - __bfloat162float(hi));
    g_Whi[idx] = hi;
    g_Wlo[idx] = lo;
}

// ---------------------------------------------------------------------------
// mma.sync bf16 RGCN GEMM: out = relu( [agg | h_in] @ B^T ), 3-term split.
// CTA: 128x128 tile, 256 threads = 8 warps in 2(M)x4(N); warp tile 64x32.
// K = 1152 in 18 chunks of 64, staged in smem as bf16 hi/lo.
// ---------------------------------------------------------------------------
#define SA_HI 0
#define SA_LO 16384
#define SB_HI 32768
#define SB_LO 49152
#define SM_TOTAL 65536
#define NCHUNK 18

__device__ __forceinline__ void ldsm_x4(uint32_t* r, uint32_t addr) {
    asm volatile("ldmatrix.sync.aligned.m8n8.x4.shared.b16 {%0,%1,%2,%3}, [%4];"
                 : "=r"(r[0]), "=r"(r[1]), "=r"(r[2]), "=r"(r[3]) : "r"(addr));
}
__device__ __forceinline__ void ldsm_x2(uint32_t* r, uint32_t addr) {
    asm volatile("ldmatrix.sync.aligned.m8n8.x2.shared.b16 {%0,%1}, [%2];"
                 : "=r"(r[0]), "=r"(r[1]) : "r"(addr));
}
__device__ __forceinline__ void mma16816(float* c, const uint32_t* a, const uint32_t* b) {
    asm volatile(
        "mma.sync.aligned.m16n8k16.row.col.f32.bf16.bf16.f32 "
        "{%0,%1,%2,%3}, {%4,%5,%6,%7}, {%8,%9}, {%0,%1,%2,%3};"
        : "+f"(c[0]), "+f"(c[1]), "+f"(c[2]), "+f"(c[3])
        : "r"(a[0]), "r"(a[1]), "r"(a[2]), "r"(a[3]), "r"(b[0]), "r"(b[1]));
}

__global__ __launch_bounds__(256, 2)
void rgcn_mma_gemm_kernel(const float* __restrict__ h_in,
                          const __nv_bfloat16* __restrict__ Whi,  // [128][1152]
                          const __nv_bfloat16* __restrict__ Wlo,
                          float* __restrict__ out) {
    extern __shared__ char dsm[];
    const uint32_t sb = smem_to_u32(dsm);
    const int tid  = threadIdx.x;
    const int wid  = tid >> 5;
    const int lane = tid & 31;
    const int warp_m = wid >> 2;        // 0..1 (64 rows)
    const int warp_n = wid & 3;         // 0..3 (32 cols)
    const int row0 = blockIdx.x * 128;

    float acc[4][4][4];
    #pragma unroll
    for (int mt = 0; mt < 4; mt++)
        #pragma unroll
        for (int nt = 0; nt < 4; nt++)
            #pragma unroll
            for (int j = 0; j < 4; j++) acc[mt][nt][j] = 0.f;

    for (int t = 0; t < NCHUNK; t++) {
        // ---- stage A chunk [128 rows][64 k] fp32 -> bf16 hi/lo, swizzled ----
        #pragma unroll
        for (int i = 0; i < 8; i++) {
            int pos = i * 1024 + tid * 4;     // elem index in [128][64]
            int r = pos >> 6, c = pos & 63;
            const float* ap = (t < 16)
                ? (g_agg + (size_t)(row0 + r) * (Rr * Hh) + t * 64 + c)
                : (h_in + (size_t)(row0 + r) * Hh + (t - 16) * 64 + c);
            float4 v = *(const float4*)ap;
            __nv_bfloat16 h0 = __float2bfloat16(v.x);
            __nv_bfloat16 h1 = __float2bfloat16(v.y);
            __nv_bfloat16 h2 = __float2bfloat16(v.z);
            __nv_bfloat16 h3 = __float2bfloat16(v.w);
            __nv_bfloat16 l0 = __float2bfloat16(v.x - __bfloat162float(h0));
            __nv_bfloat16 l1 = __float2bfloat16(v.y - __bfloat162float(h1));
            __nv_bfloat16 l2 = __float2bfloat16(v.z - __bfloat162float(h2));
            __nv_bfloat16 l3 = __float2bfloat16(v.w - __bfloat162float(h3));
            uint2 uhi, ulo;
            uhi.x = (uint32_t)__bfloat16_as_ushort(h0) | ((uint32_t)__bfloat16_as_ushort(h1) << 16);
            uhi.y = (uint32_t)__bfloat16_as_ushort(h2) | ((uint32_t)__bfloat16_as_ushort(h3) << 16);
            ulo.x = (uint32_t)__bfloat16_as_ushort(l0) | ((uint32_t)__bfloat16_as_ushort(l1) << 16);
            ulo.y = (uint32_t)__bfloat16_as_ushort(l2) | ((uint32_t)__bfloat16_as_ushort(l3) << 16);
            uint32_t off = (uint32_t)(r * 128 + (((c >> 3) ^ (r & 7)) << 4) + (c & 7) * 2);
            *(uint2*)(dsm + SA_HI + off) = uhi;
            *(uint2*)(dsm + SA_LO + off) = ulo;
        }
        // ---- stage B chunk [128 n][64 k] (pre-split bf16) ----
        #pragma unroll
        for (int i = 0; i < 8; i++) {
            int pos = i * 1024 + tid * 4;
            int r = pos >> 6, c = pos & 63;
            uint2 bh = *(const uint2*)(Whi + (size_t)r * KK + t * 64 + c);
            uint2 bl = *(const uint2*)(Wlo + (size_t)r * KK + t * 64 + c);
            uint32_t off = (uint32_t)(r * 128 + (((c >> 3) ^ (r & 7)) << 4) + (c & 7) * 2);
            *(uint2*)(dsm + SB_HI + off) = bh;
            *(uint2*)(dsm + SB_LO + off) = bl;
        }
        __syncthreads();

        // ---- 4 k16 steps per chunk ----
        #pragma unroll
        for (int ks = 0; ks < 4; ks++) {
            // B fragments (hi and lo), 4 n-tiles
            uint32_t bh[4][2], bl[4][2];
            {
                int nl = warp_n * 32 + (lane & 7);               // local n row
                int cb = (lane >> 3) & 1;                        // k half (for lanes<16)
                uint32_t boff = (uint32_t)(nl * 128 + (((ks * 2 + cb) ^ (nl & 7)) << 4));
                #pragma unroll
                for (int nt = 0; nt < 4; nt++) {
                    uint32_t a = sb + (uint32_t)(nt * 8 * 128) + boff;
                    ldsm_x2(bh[nt], SB_HI + a);
                    ldsm_x2(bl[nt], SB_LO + a);
                }
            }
            // A hi fragments, 4 m-tiles; mma vs bh and bl
            uint32_t af[4][4];
            {
                int rl = warp_m * 64 + (lane & 15);
                int cb = lane >> 4;
                uint32_t aoff = (uint32_t)(rl * 128 + (((ks * 2 + cb) ^ (rl & 7)) << 4));
                #pragma unroll
                for (int mt = 0; mt < 4; mt++)
                    ldsm_x4(af[mt], sb + SA_HI + (uint32_t)(mt * 16 * 128) + aoff);
                #pragma unroll
                for (int mt = 0; mt < 4; mt++)
                    #pragma unroll
                    for (int nt = 0; nt < 4; nt++) {
                        mma16816(acc[mt][nt], af[mt], bh[nt]);
                        mma16816(acc[mt][nt], af[mt], bl[nt]);
                    }
                // A lo fragments; mma vs bh only
                #pragma unroll
                for (int mt = 0; mt < 4; mt++)
                    ldsm_x4(af[mt], sb + SA_LO + (uint32_t)(mt * 16 * 128) + aoff);
                #pragma unroll
                for (int mt = 0; mt < 4; mt++)
                    #pragma unroll
                    for (int nt = 0; nt < 4; nt++)
                        mma16816(acc[mt][nt], af[mt], bh[nt]);
            }
        }
        __syncthreads();
    }

    // ---- epilogue: relu + store ----
    #pragma unroll
    for (int mt = 0; mt < 4; mt++) {
        int row = row0 + warp_m * 64 + mt * 16 + (lane >> 2);
        #pragma unroll
        for (int nt = 0; nt < 4; nt++) {
            int col = warp_n * 32 + nt * 8 + (lane & 3) * 2;
            float2 o0, o1;
            o0.x = fmaxf(acc[mt][nt][0], 0.f);
            o0.y = fmaxf(acc[mt][nt][1], 0.f);
            o1.x = fmaxf(acc[mt][nt][2], 0.f);
            o1.y = fmaxf(acc[mt][nt][3], 0.f);
            *(float2*)(out + (size_t)row * Hh + col) = o0;
            *(float2*)(out + (size_t)(row + 8) * Hh + col) = o1;
        }
    }
}

// ---------------------------------------------------------------------------
// Mean pooling per (graph, layer)
// ---------------------------------------------------------------------------
__global__ void pool_kernel() {
    int b = blockIdx.x / Ll, l = blockIdx.x % Ll, i = threadIdx.x;
    const float* p = g_repr + (size_t)l * Nn * Hh + (size_t)b * NPG * Hh + i;
    float s = 0.f;
    for (int n = 0; n < NPG; n++) s += p[(size_t)n * Hh];
    g_mean_buf[(b * Ll + l) * Hh + i] = s * (1.0f / NPG);
}

// ---------------------------------------------------------------------------
// Fused final head: one block per batch element, 128 threads.
// ---------------------------------------------------------------------------
__global__ void final_kernel(const float* __restrict__ rel_table,
                             const float* __restrict__ Zn,
                             const float* __restrict__ proj_W,
                             const float* __restrict__ proj_b,
                             const float* __restrict__ fc_W,
                             const float* __restrict__ fc_b,
                             const float* __restrict__ rep_seq,
                             const int* __restrict__ head_ids,
                             const int* __restrict__ tail_ids,
                             const int* __restrict__ rel_labels,
                             float* __restrict__ out)
{
    int b = blockIdx.x, i = threadIdx.x;
    __shared__ float sh_head[Ll * Hh], sh_tail[Ll * Hh], sh_gm[Ll * Hh];
    __shared__ float sh_gout[Hh], sh_hout[Hh], sh_tout[Hh];
    __shared__ float sh_e1[Kk], sh_e2[Kk];
    __shared__ float red[Hh];

    int head = head_ids[b], tail = tail_ids[b], rl = rel_labels[b];

    for (int j = i; j < Ll * Hh; j += Hh) {
        int l = j >> 7, c = j & 127;
        sh_head[j] = g_repr[(size_t)l * Nn * Hh + (size_t)head * Hh + c];
        sh_tail[j] = g_repr[(size_t)l * Nn * Hh + (size_t)tail * Hh + c];
        sh_gm[j]   = g_mean_buf[(b * Ll + l) * Hh + c];
    }
    __syncthreads();

    float bias = proj_b[i];
    float ag = bias, ah = bias, at = bias;
    for (int j = 0; j < Ll * Hh; j++) {
        float w = proj_W[j * Hh + i];
        ag = fmaf(sh_gm[j],   w, ag);
        ah = fmaf(sh_head[j], w, ah);
        at = fmaf(sh_tail[j], w, at);
    }
    sh_gout[i] = (ag >= 0.f) ? ag : 0.01f * ag;
    sh_hout[i] = ah;
    sh_tout[i] = at;
    __syncthreads();

    float lg1 = 0.f, lg2 = 0.f;
    if (i < Kk) {
        const float* z = Zn + (size_t)i * Hh;
        for (int c = 0; c < Hh; c++) {
            lg1 = fmaf(sh_hout[c], z[c], lg1);
            lg2 = fmaf(sh_tout[c], z[c], lg2);
        }
        sh_e1[i] = lg1; sh_e2[i] = lg2;
    }
    __syncthreads();
    float m1 = -1e30f, m2 = -1e30f;
    for (int k = 0; k < Kk; k++) {
        m1 = fmaxf(m1, sh_e1[k]);
        m2 = fmaxf(m2, sh_e2[k]);
    }
    __syncthreads();
    if (i < Kk) { sh_e1[i] = expf(lg1 - m1); sh_e2[i] = expf(lg2 - m2); }
    __syncthreads();
    float sum1 = 0.f, sum2 = 0.f;
    for (int k = 0; k < Kk; k++) { sum1 += sh_e1[k]; sum2 += sh_e2[k]; }
    float a1 = 0.f, a2 = 0.f;
    for (int k = 0; k < Kk; k++) {
        float zi = Zn[(size_t)k * Hh + i];
        a1 = fmaf(sh_e1[k], zi, a1);
        a2 = fmaf(sh_e2[k], zi, a2);
    }
    a1 /= sum1; a2 /= sum2;
    float sview = (1.f / (1.f + expf(-a1))) * (1.f / (1.f + expf(-a2)));

    float relv = rel_table[(size_t)rl * Hh + i];
    float v0 = sh_gout[i];
    float v1 = rep_seq[(size_t)b * Hh + i];
    float v2 = sview;

    float d[3];
    float parts[3] = {relv * v0, relv * v1, relv * v2};
    #pragma unroll
    for (int v = 0; v < 3; v++) {
        red[i] = parts[v];
        __syncthreads();
        for (int s = 64; s > 0; s >>= 1) {
            if (i < s) red[i] += red[i + s];
            __syncthreads();
        }
        d[v] = red[0];
        __syncthreads();
    }
    float dm = fmaxf(d[0], fmaxf(d[1], d[2]));
    float e0 = expf(d[0] - dm), e1 = expf(d[1] - dm), e2 = expf(d[2] - dm);
    float es = e0 + e1 + e2;
    float vag = (e0 * v0 + e1 * v1 + e2 * v2) / es;

    float part = 0.f;
    #pragma unroll
    for (int l = 0; l < Ll; l++) {
        part = fmaf(sh_head[l * Hh + i], fc_W[l * Hh + i], part);
        part = fmaf(sh_tail[l * Hh + i], fc_W[Ll * Hh + l * Hh + i], part);
    }
    part = fmaf(relv, fc_W[2 * Ll * Hh + i], part);
    part = fmaf(vag,  fc_W[2 * Ll * Hh + Hh + i], part);
    red[i] = part;
    __syncthreads();
    for (int s = 64; s > 0; s >>= 1) {
        if (i < s) red[i] += red[i + s];
        __syncthreads();
    }
    if (i == 0) out[b] = red[0] + fc_b[0];
}

// ---------------------------------------------------------------------------
extern "C" void kernel_launch(void* const* d_in, const int* in_sizes, int n_in,
                              void* d_out, int out_size) {
    const float* x         = (const float*)d_in[0];
    const float* W_rel     = (const float*)d_in[1];
    const float* W_self    = (const float*)d_in[2];
    const float* rel_table = (const float*)d_in[3];
    const float* Zn        = (const float*)d_in[4];
    const float* proj_W    = (const float*)d_in[5];
    const float* proj_b    = (const float*)d_in[6];
    const float* fc_W      = (const float*)d_in[7];
    const float* fc_b      = (const float*)d_in[8];
    const float* rep_seq   = (const float*)d_in[9];
    const int*   src       = (const int*)d_in[10];
    const int*   dst       = (const int*)d_in[11];
    const int*   etype     = (const int*)d_in[12];
    const int*   head_ids  = (const int*)d_in[14];
    const int*   tail_ids  = (const int*)d_in[15];
    const int*   rel_labels= (const int*)d_in[16];
    float* out = (float*)d_out;

    float* repr_base;
    cudaGetSymbolAddress((void**)&repr_base, g_repr);
    __nv_bfloat16* whi_base;
    __nv_bfloat16* wlo_base;
    cudaGetSymbolAddress((void**)&whi_base, g_Whi);
    cudaGetSymbolAddress((void**)&wlo_base, g_Wlo);

    cudaFuncSetAttribute(rgcn_mma_gemm_kernel,
                         cudaFuncAttributeMaxDynamicSharedMemorySize, SM_TOTAL);

    const int zero_threads = 256;
    const int zero_blocks  = (Nn * Rr * Hh / 4) / zero_threads;
    const int scat_blocks  = (Ee * 32) / 256;
    const int gemm_blocks  = Nn / 128;          // 250
    const int convw_total  = Ll * Hh * KK;

    conv_w_kernel<<<(convw_total + 255) / 256, 256>>>(W_rel, W_self);

    for (int l = 0; l < Ll; l++) {
        const float* h_in = (l == 0) ? x : (repr_base + (size_t)(l - 1) * Nn * Hh);
        float* h_out = repr_base + (size_t)l * Nn * Hh;
        zero_agg_kernel<<<zero_blocks, zero_threads>>>();
        scatter_kernel<<<scat_blocks, 256>>>(h_in, src, dst, etype);
        rgcn_mma_gemm_kernel<<<gemm_blocks, 256, SM_TOTAL>>>(
            h_in,
            whi_base + (size_t)l * Hh * KK,
            wlo_base + (size_t)l * Hh * KK,
            h_out);
    }
    pool_kernel<<<BSz * Ll, Hh>>>();
    final_kernel<<<BSz, Hh>>>(rel_table, Zn, proj_W, proj_b, fc_W, fc_b,
                              rep_seq, head_ids, tail_ids, rel_labels, out);
}

// round 6
// speedup vs baseline: 1.8276x; 1.0302x over previous
#include <cuda_runtime.h>
#include <cuda_bf16.h>
#include <math.h>
#include <cstdint>

// Problem constants (fixed by setup_inputs)
#define Nn   32000
#define Hh   128
#define Ll   3
#define Rr   8
#define Ee   512000
#define BSz  32
#define Kk   64
#define NPG  1000
#define KK   1152   // R*H + H
#define NBINS 32768

// Scratch (device globals; no runtime allocation allowed)
__device__ float g_repr[(size_t)Ll * Nn * Hh];    // 49 MB, layer-major [L,N,H]
__device__ float g_mean_buf[BSz * Ll * Hh];
// A matrix, bf16 hi/lo split, [N][1152]: cols 0..1023 = agg (gather), 1024..1151 = self h
__device__ __nv_bfloat16 g_Ahi[(size_t)Nn * KK];
__device__ __nv_bfloat16 g_Alo[(size_t)Nn * KK];
// Weights, bf16 hi/lo split, [L][n=128][k=1152] (B = W^T, K-major)
__device__ __nv_bfloat16 g_Whi[(size_t)Ll * Hh * KK];
__device__ __nv_bfloat16 g_Wlo[(size_t)Ll * Hh * KK];
// CSR by dst
__device__ int g_cnt[NBINS];
__device__ int g_off[NBINS];
__device__ int g_fill[NBINS];
__device__ uint32_t g_edges[Ee];   // src | (et << 16)

__device__ __forceinline__ uint32_t smem_to_u32(const void* smem_ptr) {
    uint32_t addr;
    asm("{ .reg .u64 tmp; cvta.to.shared.u64 tmp, %1; cvt.u32.u64 %0, tmp; }"
        : "=r"(addr) : "l"(smem_ptr));
    return addr;
}

// ---------------------------------------------------------------------------
// CSR build
// ---------------------------------------------------------------------------
__global__ void zero_cnt_kernel() {
    int i = blockIdx.x * blockDim.x + threadIdx.x;
    g_cnt[i] = 0;
}
__global__ void count_kernel(const int* __restrict__ dst) {
    int e = blockIdx.x * blockDim.x + threadIdx.x;
    if (e < Ee) atomicAdd(&g_cnt[dst[e]], 1);
}
__global__ void scan_kernel() {
    // single block, 1024 threads, 32 chunks of 1024 over NBINS
    __shared__ int wsum[32];
    int tid = threadIdx.x, lane = tid & 31, wid = tid >> 5;
    int carry = 0;
    for (int c = 0; c < NBINS / 1024; c++) {
        int idx = c * 1024 + tid;
        int v = g_cnt[idx];
        int incl = v;
        #pragma unroll
        for (int d = 1; d < 32; d <<= 1) {
            int n = __shfl_up_sync(0xffffffff, incl, d);
            if (lane >= d) incl += n;
        }
        if (lane == 31) wsum[wid] = incl;
        __syncthreads();
        if (wid == 0) {
            int s = wsum[lane];
            #pragma unroll
            for (int d = 1; d < 32; d <<= 1) {
                int n = __shfl_up_sync(0xffffffff, s, d);
                if (lane >= d) s += n;
            }
            wsum[lane] = s;
        }
        __syncthreads();
        int warp_prefix = wid ? wsum[wid - 1] : 0;
        int excl = carry + warp_prefix + incl - v;
        g_off[idx] = excl;
        g_fill[idx] = excl;
        carry += wsum[31];
        __syncthreads();
    }
}
__global__ void fill_kernel(const int* __restrict__ src,
                            const int* __restrict__ dst,
                            const int* __restrict__ et) {
    int e = blockIdx.x * blockDim.x + threadIdx.x;
    if (e >= Ee) return;
    int d = dst[e];
    int pos = atomicAdd(&g_fill[d], 1);
    g_edges[pos] = (uint32_t)src[e] | ((uint32_t)et[e] << 16);
}

// ---------------------------------------------------------------------------
// Weight pre-conversion: B[l][n][k] = W[k][n], bf16 hi/lo split
// ---------------------------------------------------------------------------
__global__ void conv_w_kernel(const float* __restrict__ W_rel,
                              const float* __restrict__ W_self) {
    size_t idx = (size_t)blockIdx.x * blockDim.x + threadIdx.x;
    if (idx >= (size_t)Ll * Hh * KK) return;
    int k = (int)(idx % KK);
    int n = (int)((idx / KK) % Hh);
    int l = (int)(idx / ((size_t)KK * Hh));
    float w = (k < Rr * Hh)
        ? W_rel[((size_t)l * Rr * Hh + k) * Hh + n]
        : W_self[((size_t)l * Hh + (k - Rr * Hh)) * Hh + n];
    __nv_bfloat16 hi = __float2bfloat16(w);
    __nv_bfloat16 lo = __float2bfloat16(w - __bfloat162float(hi));
    g_Whi[idx] = hi;
    g_Wlo[idx] = lo;
}

// ---------------------------------------------------------------------------
// x -> bf16 hi/lo split into self cols (1024..1151) of g_Ahi/g_Alo (layer 0)
// ---------------------------------------------------------------------------
__global__ void xsplit_kernel(const float* __restrict__ x) {
    int pos = blockIdx.x * blockDim.x + threadIdx.x;   // float4 id
    if (pos >= Nn * Hh / 4) return;
    int row = pos >> 5, c4 = (pos & 31) * 4;
    float4 v = *(const float4*)(x + (size_t)row * Hh + c4);
    __nv_bfloat16 h0 = __float2bfloat16(v.x), h1 = __float2bfloat16(v.y);
    __nv_bfloat16 h2 = __float2bfloat16(v.z), h3 = __float2bfloat16(v.w);
    __nv_bfloat16 l0 = __float2bfloat16(v.x - __bfloat162float(h0));
    __nv_bfloat16 l1 = __float2bfloat16(v.y - __bfloat162float(h1));
    __nv_bfloat16 l2 = __float2bfloat16(v.z - __bfloat162float(h2));
    __nv_bfloat16 l3 = __float2bfloat16(v.w - __bfloat162float(h3));
    uint2 uhi, ulo;
    uhi.x = (uint32_t)__bfloat16_as_ushort(h0) | ((uint32_t)__bfloat16_as_ushort(h1) << 16);
    uhi.y = (uint32_t)__bfloat16_as_ushort(h2) | ((uint32_t)__bfloat16_as_ushort(h3) << 16);
    ulo.x = (uint32_t)__bfloat16_as_ushort(l0) | ((uint32_t)__bfloat16_as_ushort(l1) << 16);
    ulo.y = (uint32_t)__bfloat16_as_ushort(l2) | ((uint32_t)__bfloat16_as_ushort(l3) << 16);
    size_t o = (size_t)row * KK + 1024 + c4;
    *(uint2*)(g_Ahi + o) = uhi;
    *(uint2*)(g_Alo + o) = ulo;
}

// ---------------------------------------------------------------------------
// Gather aggregation: one warp per dst node; accumulate in regs, write bf16
// hi/lo split directly into g_Ahi/g_Alo cols 0..1023.
// ---------------------------------------------------------------------------
__global__ __launch_bounds__(256)
void gather_kernel(const float* __restrict__ h) {
    int gw = (blockIdx.x * blockDim.x + threadIdx.x) >> 5;
    int lane = threadIdx.x & 31;
    if (gw >= Nn) return;
    int beg = g_off[gw];
    int end = beg + g_cnt[gw];

    float4 a0 = {0,0,0,0}, a1 = {0,0,0,0}, a2 = {0,0,0,0}, a3 = {0,0,0,0};
    float4 a4 = {0,0,0,0}, a5 = {0,0,0,0}, a6 = {0,0,0,0}, a7 = {0,0,0,0};

    for (int e = beg; e < end; e++) {
        uint32_t p = g_edges[e];             // warp-uniform broadcast load
        int s = (int)(p & 0xFFFFu);
        int r = (int)(p >> 16);
        float4 v = *(const float4*)(h + (size_t)s * Hh + lane * 4);
        switch (r) {                          // warp-uniform branch
            case 0: a0.x+=v.x; a0.y+=v.y; a0.z+=v.z; a0.w+=v.w; break;
            case 1: a1.x+=v.x; a1.y+=v.y; a1.z+=v.z; a1.w+=v.w; break;
            case 2: a2.x+=v.x; a2.y+=v.y; a2.z+=v.z; a2.w+=v.w; break;
            case 3: a3.x+=v.x; a3.y+=v.y; a3.z+=v.z; a3.w+=v.w; break;
            case 4: a4.x+=v.x; a4.y+=v.y; a4.z+=v.z; a4.w+=v.w; break;
            case 5: a5.x+=v.x; a5.y+=v.y; a5.z+=v.z; a5.w+=v.w; break;
            case 6: a6.x+=v.x; a6.y+=v.y; a6.z+=v.z; a6.w+=v.w; break;
            default: a7.x+=v.x; a7.y+=v.y; a7.z+=v.z; a7.w+=v.w; break;
        }
    }

    size_t base = (size_t)gw * KK + lane * 4;
    #define SPLIT_WRITE(acc, rr) do { \
        __nv_bfloat16 h0 = __float2bfloat16(acc.x), h1 = __float2bfloat16(acc.y); \
        __nv_bfloat16 h2 = __float2bfloat16(acc.z), h3 = __float2bfloat16(acc.w); \
        __nv_bfloat16 l0 = __float2bfloat16(acc.x - __bfloat162float(h0)); \
        __nv_bfloat16 l1 = __float2bfloat16(acc.y - __bfloat162float(h1)); \
        __nv_bfloat16 l2 = __float2bfloat16(acc.z - __bfloat162float(h2)); \
        __nv_bfloat16 l3 = __float2bfloat16(acc.w - __bfloat162float(h3)); \
        uint2 uhi, ulo; \
        uhi.x = (uint32_t)__bfloat16_as_ushort(h0) | ((uint32_t)__bfloat16_as_ushort(h1) << 16); \
        uhi.y = (uint32_t)__bfloat16_as_ushort(h2) | ((uint32_t)__bfloat16_as_ushort(h3) << 16); \
        ulo.x = (uint32_t)__bfloat16_as_ushort(l0) | ((uint32_t)__bfloat16_as_ushort(l1) << 16); \
        ulo.y = (uint32_t)__bfloat16_as_ushort(l2) | ((uint32_t)__bfloat16_as_ushort(l3) << 16); \
        *(uint2*)(g_Ahi + base + rr * Hh) = uhi; \
        *(uint2*)(g_Alo + base + rr * Hh) = ulo; \
    } while (0)
    SPLIT_WRITE(a0, 0); SPLIT_WRITE(a1, 1); SPLIT_WRITE(a2, 2); SPLIT_WRITE(a3, 3);
    SPLIT_WRITE(a4, 4); SPLIT_WRITE(a5, 5); SPLIT_WRITE(a6, 6); SPLIT_WRITE(a7, 7);
    #undef SPLIT_WRITE
}

// ---------------------------------------------------------------------------
// mma.sync bf16 GEMM: out = relu( A @ B^T ), 3-term split; A pre-split bf16.
// CTA 128x128, 256 thr (8 warps 2x4), K=1152 in 18 chunks of 64, cp.async stage.
// Epilogue writes fp32 repr AND bf16 hi/lo self cols for the next layer.
// ---------------------------------------------------------------------------
#define SA_HI 0
#define SA_LO 16384
#define SB_HI 32768
#define SB_LO 49152
#define SM_TOTAL 65536
#define NCHUNK 18

__device__ __forceinline__ void ldsm_x4(uint32_t* r, uint32_t addr) {
    asm volatile("ldmatrix.sync.aligned.m8n8.x4.shared.b16 {%0,%1,%2,%3}, [%4];"
                 : "=r"(r[0]), "=r"(r[1]), "=r"(r[2]), "=r"(r[3]) : "r"(addr));
}
__device__ __forceinline__ void ldsm_x2(uint32_t* r, uint32_t addr) {
    asm volatile("ldmatrix.sync.aligned.m8n8.x2.shared.b16 {%0,%1}, [%2];"
                 : "=r"(r[0]), "=r"(r[1]) : "r"(addr));
}
__device__ __forceinline__ void mma16816(float* c, const uint32_t* a, const uint32_t* b) {
    asm volatile(
        "mma.sync.aligned.m16n8k16.row.col.f32.bf16.bf16.f32 "
        "{%0,%1,%2,%3}, {%4,%5,%6,%7}, {%8,%9}, {%0,%1,%2,%3};"
        : "+f"(c[0]), "+f"(c[1]), "+f"(c[2]), "+f"(c[3])
        : "r"(a[0]), "r"(a[1]), "r"(a[2]), "r"(a[3]), "r"(b[0]), "r"(b[1]));
}
__device__ __forceinline__ void cp16(uint32_t smem_dst, const void* gsrc) {
    asm volatile("cp.async.cg.shared.global [%0], [%1], 16;"
                 :: "r"(smem_dst), "l"(gsrc));
}

__global__ __launch_bounds__(256, 2)
void rgcn_mma_gemm_kernel(const __nv_bfloat16* __restrict__ Whi,  // [128][1152]
                          const __nv_bfloat16* __restrict__ Wlo,
                          float* __restrict__ out) {
    extern __shared__ char dsm[];
    const uint32_t sb = smem_to_u32(dsm);
    const int tid  = threadIdx.x;
    const int wid  = tid >> 5;
    const int lane = tid & 31;
    const int warp_m = wid >> 2;
    const int warp_n = wid & 3;
    const int row0 = blockIdx.x * 128;

    float acc[4][4][4];
    #pragma unroll
    for (int mt = 0; mt < 4; mt++)
        #pragma unroll
        for (int nt = 0; nt < 4; nt++)
            #pragma unroll
            for (int j = 0; j < 4; j++) acc[mt][nt][j] = 0.f;

    for (int t = 0; t < NCHUNK; t++) {
        const __nv_bfloat16* ah = g_Ahi + (size_t)row0 * KK + t * 64;
        const __nv_bfloat16* al = g_Alo + (size_t)row0 * KK + t * 64;
        const __nv_bfloat16* bh = Whi + t * 64;
        const __nv_bfloat16* bl = Wlo + t * 64;
        #pragma unroll
        for (int i = 0; i < 4; i++) {
            int pos = i * 256 + tid;         // 16B granule id in [128][8]
            int r = pos >> 3, cb = pos & 7;
            uint32_t soff = (uint32_t)(r * 128 + ((cb ^ (r & 7)) << 4));
            size_t goff = (size_t)r * KK + cb * 8;
            cp16(sb + SA_HI + soff, ah + goff);
            cp16(sb + SA_LO + soff, al + goff);
            cp16(sb + SB_HI + soff, bh + goff);
            cp16(sb + SB_LO + soff, bl + goff);
        }
        asm volatile("cp.async.commit_group;");
        asm volatile("cp.async.wait_group 0;");
        __syncthreads();

        #pragma unroll
        for (int ks = 0; ks < 4; ks++) {
            uint32_t bhf[4][2], blf[4][2];
            {
                int nl = warp_n * 32 + (lane & 7);
                int cb = (lane >> 3) & 1;
                uint32_t boff = (uint32_t)(nl * 128 + (((ks * 2 + cb) ^ (nl & 7)) << 4));
                #pragma unroll
                for (int nt = 0; nt < 4; nt++) {
                    uint32_t a = sb + (uint32_t)(nt * 8 * 128) + boff;
                    ldsm_x2(bhf[nt], SB_HI + a);
                    ldsm_x2(blf[nt], SB_LO + a);
                }
            }
            uint32_t af[4][4];
            {
                int rl = warp_m * 64 + (lane & 15);
                int cb = lane >> 4;
                uint32_t aoff = (uint32_t)(rl * 128 + (((ks * 2 + cb) ^ (rl & 7)) << 4));
                #pragma unroll
                for (int mt = 0; mt < 4; mt++)
                    ldsm_x4(af[mt], sb + SA_HI + (uint32_t)(mt * 16 * 128) + aoff);
                #pragma unroll
                for (int mt = 0; mt < 4; mt++)
                    #pragma unroll
                    for (int nt = 0; nt < 4; nt++) {
                        mma16816(acc[mt][nt], af[mt], bhf[nt]);
                        mma16816(acc[mt][nt], af[mt], blf[nt]);
                    }
                #pragma unroll
                for (int mt = 0; mt < 4; mt++)
                    ldsm_x4(af[mt], sb + SA_LO + (uint32_t)(mt * 16 * 128) + aoff);
                #pragma unroll
                for (int mt = 0; mt < 4; mt++)
                    #pragma unroll
                    for (int nt = 0; nt < 4; nt++)
                        mma16816(acc[mt][nt], af[mt], bhf[nt]);
            }
        }
        __syncthreads();
    }

    // ---- epilogue: relu + store fp32 repr + bf16 hi/lo self cols ----
    #pragma unroll
    for (int mt = 0; mt < 4; mt++) {
        int row = row0 + warp_m * 64 + mt * 16 + (lane >> 2);
        #pragma unroll
        for (int nt = 0; nt < 4; nt++) {
            int col = warp_n * 32 + nt * 8 + (lane & 3) * 2;
            #pragma unroll
            for (int half = 0; half < 2; half++) {
                int rr = row + half * 8;
                float ox = fmaxf(acc[mt][nt][half * 2 + 0], 0.f);
                float oy = fmaxf(acc[mt][nt][half * 2 + 1], 0.f);
                float2 o = make_float2(ox, oy);
                *(float2*)(out + (size_t)rr * Hh + col) = o;
                __nv_bfloat16 h0 = __float2bfloat16(ox);
                __nv_bfloat16 h1 = __float2bfloat16(oy);
                __nv_bfloat16 l0 = __float2bfloat16(ox - __bfloat162float(h0));
                __nv_bfloat16 l1 = __float2bfloat16(oy - __bfloat162float(h1));
                uint32_t uhi = (uint32_t)__bfloat16_as_ushort(h0) | ((uint32_t)__bfloat16_as_ushort(h1) << 16);
                uint32_t ulo = (uint32_t)__bfloat16_as_ushort(l0) | ((uint32_t)__bfloat16_as_ushort(l1) << 16);
                size_t so = (size_t)rr * KK + 1024 + col;
                *(uint32_t*)(g_Ahi + so) = uhi;
                *(uint32_t*)(g_Alo + so) = ulo;
            }
        }
    }
}

// ---------------------------------------------------------------------------
// Mean pooling per (graph, layer)
// ---------------------------------------------------------------------------
__global__ void pool_kernel() {
    int b = blockIdx.x / Ll, l = blockIdx.x % Ll, i = threadIdx.x;
    const float* p = g_repr + (size_t)l * Nn * Hh + (size_t)b * NPG * Hh + i;
    float s = 0.f;
    for (int n = 0; n < NPG; n++) s += p[(size_t)n * Hh];
    g_mean_buf[(b * Ll + l) * Hh + i] = s * (1.0f / NPG);
}

// ---------------------------------------------------------------------------
// Fused final head: one block per batch element, 128 threads.
// ---------------------------------------------------------------------------
__global__ void final_kernel(const float* __restrict__ rel_table,
                             const float* __restrict__ Zn,
                             const float* __restrict__ proj_W,
                             const float* __restrict__ proj_b,
                             const float* __restrict__ fc_W,
                             const float* __restrict__ fc_b,
                             const float* __restrict__ rep_seq,
                             const int* __restrict__ head_ids,
                             const int* __restrict__ tail_ids,
                             const int* __restrict__ rel_labels,
                             float* __restrict__ out)
{
    int b = blockIdx.x, i = threadIdx.x;
    __shared__ float sh_head[Ll * Hh], sh_tail[Ll * Hh], sh_gm[Ll * Hh];
    __shared__ float sh_gout[Hh], sh_hout[Hh], sh_tout[Hh];
    __shared__ float sh_e1[Kk], sh_e2[Kk];
    __shared__ float red[Hh];

    int head = head_ids[b], tail = tail_ids[b], rl = rel_labels[b];

    for (int j = i; j < Ll * Hh; j += Hh) {
        int l = j >> 7, c = j & 127;
        sh_head[j] = g_repr[(size_t)l * Nn * Hh + (size_t)head * Hh + c];
        sh_tail[j] = g_repr[(size_t)l * Nn * Hh + (size_t)tail * Hh + c];
        sh_gm[j]   = g_mean_buf[(b * Ll + l) * Hh + c];
    }
    __syncthreads();

    float bias = proj_b[i];
    float ag = bias, ah = bias, at = bias;
    for (int j = 0; j < Ll * Hh; j++) {
        float w = proj_W[j * Hh + i];
        ag = fmaf(sh_gm[j],   w, ag);
        ah = fmaf(sh_head[j], w, ah);
        at = fmaf(sh_tail[j], w, at);
    }
    sh_gout[i] = (ag >= 0.f) ? ag : 0.01f * ag;
    sh_hout[i] = ah;
    sh_tout[i] = at;
    __syncthreads();

    float lg1 = 0.f, lg2 = 0.f;
    if (i < Kk) {
        const float* z = Zn + (size_t)i * Hh;
        for (int c = 0; c < Hh; c++) {
            lg1 = fmaf(sh_hout[c], z[c], lg1);
            lg2 = fmaf(sh_tout[c], z[c], lg2);
        }
        sh_e1[i] = lg1; sh_e2[i] = lg2;
    }
    __syncthreads();
    float m1 = -1e30f, m2 = -1e30f;
    for (int k = 0; k < Kk; k++) {
        m1 = fmaxf(m1, sh_e1[k]);
        m2 = fmaxf(m2, sh_e2[k]);
    }
    __syncthreads();
    if (i < Kk) { sh_e1[i] = expf(lg1 - m1); sh_e2[i] = expf(lg2 - m2); }
    __syncthreads();
    float sum1 = 0.f, sum2 = 0.f;
    for (int k = 0; k < Kk; k++) { sum1 += sh_e1[k]; sum2 += sh_e2[k]; }
    float a1 = 0.f, a2 = 0.f;
    for (int k = 0; k < Kk; k++) {
        float zi = Zn[(size_t)k * Hh + i];
        a1 = fmaf(sh_e1[k], zi, a1);
        a2 = fmaf(sh_e2[k], zi, a2);
    }
    a1 /= sum1; a2 /= sum2;
    float sview = (1.f / (1.f + expf(-a1))) * (1.f / (1.f + expf(-a2)));

    float relv = rel_table[(size_t)rl * Hh + i];
    float v0 = sh_gout[i];
    float v1 = rep_seq[(size_t)b * Hh + i];
    float v2 = sview;

    float d[3];
    float parts[3] = {relv * v0, relv * v1, relv * v2};
    #pragma unroll
    for (int v = 0; v < 3; v++) {
        red[i] = parts[v];
        __syncthreads();
        for (int s = 64; s > 0; s >>= 1) {
            if (i < s) red[i] += red[i + s];
            __syncthreads();
        }
        d[v] = red[0];
        __syncthreads();
    }
    float dm = fmaxf(d[0], fmaxf(d[1], d[2]));
    float e0 = expf(d[0] - dm), e1 = expf(d[1] - dm), e2 = expf(d[2] - dm);
    float es = e0 + e1 + e2;
    float vag = (e0 * v0 + e1 * v1 + e2 * v2) / es;

    float part = 0.f;
    #pragma unroll
    for (int l = 0; l < Ll; l++) {
        part = fmaf(sh_head[l * Hh + i], fc_W[l * Hh + i], part);
        part = fmaf(sh_tail[l * Hh + i], fc_W[Ll * Hh + l * Hh + i], part);
    }
    part = fmaf(relv, fc_W[2 * Ll * Hh + i], part);
    part = fmaf(vag,  fc_W[2 * Ll * Hh + Hh + i], part);
    red[i] = part;
    __syncthreads();
    for (int s = 64; s > 0; s >>= 1) {
        if (i < s) red[i] += red[i + s];
        __syncthreads();
    }
    if (i == 0) out[b] = red[0] + fc_b[0];
}

// ---------------------------------------------------------------------------
extern "C" void kernel_launch(void* const* d_in, const int* in_sizes, int n_in,
                              void* d_out, int out_size) {
    const float* x         = (const float*)d_in[0];
    const float* W_rel     = (const float*)d_in[1];
    const float* W_self    = (const float*)d_in[2];
    const float* rel_table = (const float*)d_in[3];
    const float* Zn        = (const float*)d_in[4];
    const float* proj_W    = (const float*)d_in[5];
    const float* proj_b    = (const float*)d_in[6];
    const float* fc_W      = (const float*)d_in[7];
    const float* fc_b      = (const float*)d_in[8];
    const float* rep_seq   = (const float*)d_in[9];
    const int*   src       = (const int*)d_in[10];
    const int*   dst       = (const int*)d_in[11];
    const int*   etype     = (const int*)d_in[12];
    const int*   head_ids  = (const int*)d_in[14];
    const int*   tail_ids  = (const int*)d_in[15];
    const int*   rel_labels= (const int*)d_in[16];
    float* out = (float*)d_out;

    float* repr_base;
    cudaGetSymbolAddress((void**)&repr_base, g_repr);
    __nv_bfloat16* whi_base;
    __nv_bfloat16* wlo_base;
    cudaGetSymbolAddress((void**)&whi_base, g_Whi);
    cudaGetSymbolAddress((void**)&wlo_base, g_Wlo);

    cudaFuncSetAttribute(rgcn_mma_gemm_kernel,
                         cudaFuncAttributeMaxDynamicSharedMemorySize, SM_TOTAL);

    // one-time per launch: weights, x self-cols, CSR
    conv_w_kernel<<<(Ll * Hh * KK + 255) / 256, 256>>>(W_rel, W_self);
    xsplit_kernel<<<(Nn * Hh / 4 + 255) / 256, 256>>>(x);
    zero_cnt_kernel<<<NBINS / 256, 256>>>();
    count_kernel<<<(Ee + 255) / 256, 256>>>(dst);
    scan_kernel<<<1, 1024>>>();
    fill_kernel<<<(Ee + 255) / 256, 256>>>(src, dst, etype);

    const int gemm_blocks = Nn / 128;           // 250
    for (int l = 0; l < Ll; l++) {
        const float* h_in = (l == 0) ? x : (repr_base + (size_t)(l - 1) * Nn * Hh);
        float* h_out = repr_base + (size_t)l * Nn * Hh;
        gather_kernel<<<(Nn * 32) / 256, 256>>>(h_in);
        rgcn_mma_gemm_kernel<<<gemm_blocks, 256, SM_TOTAL>>>(
            whi_base + (size_t)l * Hh * KK,
            wlo_base + (size_t)l * Hh * KK,
            h_out);
    }
    pool_kernel<<<BSz * Ll, Hh>>>();
    final_kernel<<<BSz, Hh>>>(rel_table, Zn, proj_W, proj_b, fc_W, fc_b,
                              rep_seq, head_ids, tail_ids, rel_labels, out);
}

// round 7
// speedup vs baseline: 2.1037x; 1.1511x over previous
#include <cuda_runtime.h>
#include <cuda_bf16.h>
#include <math.h>
#include <cstdint>

// Problem constants (fixed by setup_inputs)
#define Nn   32000
#define Hh   128
#define Ll   3
#define Rr   8
#define Ee   512000
#define BSz  32
#define Kk   64
#define NPG  1000
#define KK   1152   // R*H + H
#define NBINS 32768

// Scratch (device globals; no runtime allocation allowed)
__device__ float g_repr[(size_t)Ll * Nn * Hh];    // [L,N,H]
__device__ float g_mean_buf[BSz * Ll * Hh];
__device__ float g_pool_part[BSz * Ll * 8 * Hh];  // [b,l,chunk,ch]
// A matrix, bf16 hi/lo split, [N][1152]: cols 0..1023 = agg, 1024..1151 = self h
__device__ __nv_bfloat16 g_Ahi[(size_t)Nn * KK];
__device__ __nv_bfloat16 g_Alo[(size_t)Nn * KK];
// Weights, bf16 hi/lo split, [L][n=128][k=1152] (B = W^T, K-major)
__device__ __nv_bfloat16 g_Whi[(size_t)Ll * Hh * KK];
__device__ __nv_bfloat16 g_Wlo[(size_t)Ll * Hh * KK];
// CSR by dst
__device__ int g_cnt[NBINS];
__device__ int g_off[NBINS];
__device__ int g_fill[NBINS];
__device__ uint32_t g_edges[Ee];   // src | (et << 16)

__device__ __forceinline__ uint32_t smem_to_u32(const void* smem_ptr) {
    uint32_t addr;
    asm("{ .reg .u64 tmp; cvta.to.shared.u64 tmp, %1; cvt.u32.u64 %0, tmp; }"
        : "=r"(addr) : "l"(smem_ptr));
    return addr;
}

// ---------------------------------------------------------------------------
// CSR build
// ---------------------------------------------------------------------------
__global__ void zero_cnt_kernel() {
    int i = blockIdx.x * blockDim.x + threadIdx.x;
    g_cnt[i] = 0;
}
__global__ void count_kernel(const int* __restrict__ dst) {
    int e = blockIdx.x * blockDim.x + threadIdx.x;
    if (e < Ee) atomicAdd(&g_cnt[dst[e]], 1);
}
__global__ void scan_kernel() {
    __shared__ int wsum[32];
    int tid = threadIdx.x, lane = tid & 31, wid = tid >> 5;
    int carry = 0;
    for (int c = 0; c < NBINS / 1024; c++) {
        int idx = c * 1024 + tid;
        int v = g_cnt[idx];
        int incl = v;
        #pragma unroll
        for (int d = 1; d < 32; d <<= 1) {
            int n = __shfl_up_sync(0xffffffff, incl, d);
            if (lane >= d) incl += n;
        }
        if (lane == 31) wsum[wid] = incl;
        __syncthreads();
        if (wid == 0) {
            int s = wsum[lane];
            #pragma unroll
            for (int d = 1; d < 32; d <<= 1) {
                int n = __shfl_up_sync(0xffffffff, s, d);
                if (lane >= d) s += n;
            }
            wsum[lane] = s;
        }
        __syncthreads();
        int warp_prefix = wid ? wsum[wid - 1] : 0;
        int excl = carry + warp_prefix + incl - v;
        g_off[idx] = excl;
        g_fill[idx] = excl;
        carry += wsum[31];
        __syncthreads();
    }
}
__global__ void fill_kernel(const int* __restrict__ src,
                            const int* __restrict__ dst,
                            const int* __restrict__ et) {
    int e = blockIdx.x * blockDim.x + threadIdx.x;
    if (e >= Ee) return;
    int d = dst[e];
    int pos = atomicAdd(&g_fill[d], 1);
    g_edges[pos] = (uint32_t)src[e] | ((uint32_t)et[e] << 16);
}

// ---------------------------------------------------------------------------
// Weight pre-conversion: B[l][n][k] = W[k][n], bf16 hi/lo split
// ---------------------------------------------------------------------------
__global__ void conv_w_kernel(const float* __restrict__ W_rel,
                              const float* __restrict__ W_self) {
    size_t idx = (size_t)blockIdx.x * blockDim.x + threadIdx.x;
    if (idx >= (size_t)Ll * Hh * KK) return;
    int k = (int)(idx % KK);
    int n = (int)((idx / KK) % Hh);
    int l = (int)(idx / ((size_t)KK * Hh));
    float w = (k < Rr * Hh)
        ? W_rel[((size_t)l * Rr * Hh + k) * Hh + n]
        : W_self[((size_t)l * Hh + (k - Rr * Hh)) * Hh + n];
    __nv_bfloat16 hi = __float2bfloat16(w);
    __nv_bfloat16 lo = __float2bfloat16(w - __bfloat162float(hi));
    g_Whi[idx] = hi;
    g_Wlo[idx] = lo;
}

// ---------------------------------------------------------------------------
// x -> bf16 hi/lo split into self cols (1024..1151)
// ---------------------------------------------------------------------------
__global__ void xsplit_kernel(const float* __restrict__ x) {
    int pos = blockIdx.x * blockDim.x + threadIdx.x;
    if (pos >= Nn * Hh / 4) return;
    int row = pos >> 5, c4 = (pos & 31) * 4;
    float4 v = *(const float4*)(x + (size_t)row * Hh + c4);
    __nv_bfloat16 h0 = __float2bfloat16(v.x), h1 = __float2bfloat16(v.y);
    __nv_bfloat16 h2 = __float2bfloat16(v.z), h3 = __float2bfloat16(v.w);
    __nv_bfloat16 l0 = __float2bfloat16(v.x - __bfloat162float(h0));
    __nv_bfloat16 l1 = __float2bfloat16(v.y - __bfloat162float(h1));
    __nv_bfloat16 l2 = __float2bfloat16(v.z - __bfloat162float(h2));
    __nv_bfloat16 l3 = __float2bfloat16(v.w - __bfloat162float(h3));
    uint2 uhi, ulo;
    uhi.x = (uint32_t)__bfloat16_as_ushort(h0) | ((uint32_t)__bfloat16_as_ushort(h1) << 16);
    uhi.y = (uint32_t)__bfloat16_as_ushort(h2) | ((uint32_t)__bfloat16_as_ushort(h3) << 16);
    ulo.x = (uint32_t)__bfloat16_as_ushort(l0) | ((uint32_t)__bfloat16_as_ushort(l1) << 16);
    ulo.y = (uint32_t)__bfloat16_as_ushort(l2) | ((uint32_t)__bfloat16_as_ushort(l3) << 16);
    size_t o = (size_t)row * KK + 1024 + c4;
    *(uint2*)(g_Ahi + o) = uhi;
    *(uint2*)(g_Alo + o) = ulo;
}

// ---------------------------------------------------------------------------
// Gather: one warp per dst node. Edge words loaded lane-parallel (batch of 32),
// broadcast via shfl; body 2-way unrolled for h-load MLP.
// ---------------------------------------------------------------------------
__global__ __launch_bounds__(256)
void gather_kernel(const float* __restrict__ h) {
    int gw = (blockIdx.x * blockDim.x + threadIdx.x) >> 5;
    int lane = threadIdx.x & 31;
    if (gw >= Nn) return;
    int beg = g_off[gw];
    int cnt = g_cnt[gw];

    float4 a0 = {0,0,0,0}, a1 = {0,0,0,0}, a2 = {0,0,0,0}, a3 = {0,0,0,0};
    float4 a4 = {0,0,0,0}, a5 = {0,0,0,0}, a6 = {0,0,0,0}, a7 = {0,0,0,0};

    #define ACC_ADD(p, v) do { \
        switch ((p) >> 16) { \
            case 0: a0.x+=v.x; a0.y+=v.y; a0.z+=v.z; a0.w+=v.w; break; \
            case 1: a1.x+=v.x; a1.y+=v.y; a1.z+=v.z; a1.w+=v.w; break; \
            case 2: a2.x+=v.x; a2.y+=v.y; a2.z+=v.z; a2.w+=v.w; break; \
            case 3: a3.x+=v.x; a3.y+=v.y; a3.z+=v.z; a3.w+=v.w; break; \
            case 4: a4.x+=v.x; a4.y+=v.y; a4.z+=v.z; a4.w+=v.w; break; \
            case 5: a5.x+=v.x; a5.y+=v.y; a5.z+=v.z; a5.w+=v.w; break; \
            case 6: a6.x+=v.x; a6.y+=v.y; a6.z+=v.z; a6.w+=v.w; break; \
            default: a7.x+=v.x; a7.y+=v.y; a7.z+=v.z; a7.w+=v.w; break; \
        } \
    } while (0)

    for (int base = 0; base < cnt; base += 32) {
        int m = min(32, cnt - base);
        uint32_t myp = (lane < m) ? g_edges[beg + base + lane] : 0u;
        int j = 0;
        for (; j + 3 < m; j += 4) {
            uint32_t p0 = __shfl_sync(0xffffffffu, myp, j);
            uint32_t p1 = __shfl_sync(0xffffffffu, myp, j + 1);
            uint32_t p2 = __shfl_sync(0xffffffffu, myp, j + 2);
            uint32_t p3 = __shfl_sync(0xffffffffu, myp, j + 3);
            float4 v0 = *(const float4*)(h + (size_t)(p0 & 0xffffu) * Hh + lane * 4);
            float4 v1 = *(const float4*)(h + (size_t)(p1 & 0xffffu) * Hh + lane * 4);
            float4 v2 = *(const float4*)(h + (size_t)(p2 & 0xffffu) * Hh + lane * 4);
            float4 v3 = *(const float4*)(h + (size_t)(p3 & 0xffffu) * Hh + lane * 4);
            ACC_ADD(p0, v0); ACC_ADD(p1, v1); ACC_ADD(p2, v2); ACC_ADD(p3, v3);
        }
        for (; j < m; j++) {
            uint32_t p = __shfl_sync(0xffffffffu, myp, j);
            float4 v = *(const float4*)(h + (size_t)(p & 0xffffu) * Hh + lane * 4);
            ACC_ADD(p, v);
        }
    }
    #undef ACC_ADD

    size_t base = (size_t)gw * KK + lane * 4;
    #define SPLIT_WRITE(acc, rr) do { \
        __nv_bfloat16 h0 = __float2bfloat16(acc.x), h1 = __float2bfloat16(acc.y); \
        __nv_bfloat16 h2 = __float2bfloat16(acc.z), h3 = __float2bfloat16(acc.w); \
        __nv_bfloat16 l0 = __float2bfloat16(acc.x - __bfloat162float(h0)); \
        __nv_bfloat16 l1 = __float2bfloat16(acc.y - __bfloat162float(h1)); \
        __nv_bfloat16 l2 = __float2bfloat16(acc.z - __bfloat162float(h2)); \
        __nv_bfloat16 l3 = __float2bfloat16(acc.w - __bfloat162float(h3)); \
        uint2 uhi, ulo; \
        uhi.x = (uint32_t)__bfloat16_as_ushort(h0) | ((uint32_t)__bfloat16_as_ushort(h1) << 16); \
        uhi.y = (uint32_t)__bfloat16_as_ushort(h2) | ((uint32_t)__bfloat16_as_ushort(h3) << 16); \
        ulo.x = (uint32_t)__bfloat16_as_ushort(l0) | ((uint32_t)__bfloat16_as_ushort(l1) << 16); \
        ulo.y = (uint32_t)__bfloat16_as_ushort(l2) | ((uint32_t)__bfloat16_as_ushort(l3) << 16); \
        *(uint2*)(g_Ahi + base + rr * Hh) = uhi; \
        *(uint2*)(g_Alo + base + rr * Hh) = ulo; \
    } while (0)
    SPLIT_WRITE(a0, 0); SPLIT_WRITE(a1, 1); SPLIT_WRITE(a2, 2); SPLIT_WRITE(a3, 3);
    SPLIT_WRITE(a4, 4); SPLIT_WRITE(a5, 5); SPLIT_WRITE(a6, 6); SPLIT_WRITE(a7, 7);
    #undef SPLIT_WRITE
}

// ---------------------------------------------------------------------------
// mma.sync bf16 GEMM, 2-stage cp.async pipeline, K-chunks of 32.
// CTA 128x128, 256 thr (2x4 warps), 80-byte padded smem rows (conflict-free
// ldmatrix without swizzle). out = relu(A @ B^T), 3-term bf16 split.
// ---------------------------------------------------------------------------
#define CH    32                 // k per chunk
#define NCH   36                 // 1152 / 32
#define ROWB  80                 // padded row bytes (32 bf16 = 64B data + 16B pad)
#define BUFB  (128 * ROWB)       // 10240 bytes per matrix buffer
#define STAGEB (4 * BUFB)        // Ahi, Alo, Bhi, Blo
#define SM_TOTAL (2 * STAGEB)    // 81920

__device__ __forceinline__ void ldsm_x4(uint32_t* r, uint32_t addr) {
    asm volatile("ldmatrix.sync.aligned.m8n8.x4.shared.b16 {%0,%1,%2,%3}, [%4];"
                 : "=r"(r[0]), "=r"(r[1]), "=r"(r[2]), "=r"(r[3]) : "r"(addr));
}
__device__ __forceinline__ void ldsm_x2(uint32_t* r, uint32_t addr) {
    asm volatile("ldmatrix.sync.aligned.m8n8.x2.shared.b16 {%0,%1}, [%2];"
                 : "=r"(r[0]), "=r"(r[1]) : "r"(addr));
}
__device__ __forceinline__ void mma16816(float* c, const uint32_t* a, const uint32_t* b) {
    asm volatile(
        "mma.sync.aligned.m16n8k16.row.col.f32.bf16.bf16.f32 "
        "{%0,%1,%2,%3}, {%4,%5,%6,%7}, {%8,%9}, {%0,%1,%2,%3};"
        : "+f"(c[0]), "+f"(c[1]), "+f"(c[2]), "+f"(c[3])
        : "r"(a[0]), "r"(a[1]), "r"(a[2]), "r"(a[3]), "r"(b[0]), "r"(b[1]));
}
__device__ __forceinline__ void cp16(uint32_t smem_dst, const void* gsrc) {
    asm volatile("cp.async.cg.shared.global [%0], [%1], 16;"
                 :: "r"(smem_dst), "l"(gsrc));
}

__global__ __launch_bounds__(256, 2)
void rgcn_mma_gemm_kernel(const __nv_bfloat16* __restrict__ Whi,
                          const __nv_bfloat16* __restrict__ Wlo,
                          float* __restrict__ out) {
    extern __shared__ char dsm[];
    const uint32_t sb = smem_to_u32(dsm);
    const int tid  = threadIdx.x;
    const int wid  = tid >> 5;
    const int lane = tid & 31;
    const int warp_m = wid >> 2;
    const int warp_n = wid & 3;
    const int row0 = blockIdx.x * 128;

    const __nv_bfloat16* ah_base = g_Ahi + (size_t)row0 * KK;
    const __nv_bfloat16* al_base = g_Alo + (size_t)row0 * KK;

    float acc[4][4][4];
    #pragma unroll
    for (int mt = 0; mt < 4; mt++)
        #pragma unroll
        for (int nt = 0; nt < 4; nt++)
            #pragma unroll
            for (int j = 0; j < 4; j++) acc[mt][nt][j] = 0.f;

    // stage loader: 512 granules of 16B per buffer, 2 per thread per buffer
    auto issue_stage = [&](int t, int s) {
        uint32_t sbase = sb + s * STAGEB;
        const __nv_bfloat16* ah = ah_base + t * CH;
        const __nv_bfloat16* al = al_base + t * CH;
        const __nv_bfloat16* bh = Whi + t * CH;
        const __nv_bfloat16* bl = Wlo + t * CH;
        #pragma unroll
        for (int i = 0; i < 2; i++) {
            int g = i * 256 + tid;
            int r = g >> 2, cb = g & 3;
            uint32_t soff = (uint32_t)(r * ROWB + cb * 16);
            size_t goff = (size_t)r * KK + cb * 8;
            cp16(sbase + 0 * BUFB + soff, ah + goff);
            cp16(sbase + 1 * BUFB + soff, al + goff);
            cp16(sbase + 2 * BUFB + soff, bh + goff);
            cp16(sbase + 3 * BUFB + soff, bl + goff);
        }
        asm volatile("cp.async.commit_group;");
    };

    issue_stage(0, 0);

    for (int t = 0; t < NCH; t++) {
        asm volatile("cp.async.wait_group 0;");
        __syncthreads();
        if (t + 1 < NCH) issue_stage(t + 1, (t + 1) & 1);

        uint32_t sbase = sb + (t & 1) * STAGEB;
        #pragma unroll
        for (int ks = 0; ks < 2; ks++) {
            uint32_t bhf[4][2], blf[4][2];
            {
                int cb = (lane >> 3) & 1;
                #pragma unroll
                for (int nt = 0; nt < 4; nt++) {
                    int nl = warp_n * 32 + nt * 8 + (lane & 7);
                    uint32_t a = sbase + (uint32_t)(nl * ROWB + (ks * 2 + cb) * 16);
                    ldsm_x2(bhf[nt], 2 * BUFB + a);
                    ldsm_x2(blf[nt], 3 * BUFB + a);
                }
            }
            uint32_t af[4][4];
            {
                int cb = lane >> 4;
                #pragma unroll
                for (int mt = 0; mt < 4; mt++) {
                    int rl = warp_m * 64 + mt * 16 + (lane & 15);
                    uint32_t a = sbase + (uint32_t)(rl * ROWB + (ks * 2 + cb) * 16);
                    ldsm_x4(af[mt], 0 * BUFB + a);
                }
                #pragma unroll
                for (int mt = 0; mt < 4; mt++)
                    #pragma unroll
                    for (int nt = 0; nt < 4; nt++) {
                        mma16816(acc[mt][nt], af[mt], bhf[nt]);
                        mma16816(acc[mt][nt], af[mt], blf[nt]);
                    }
                #pragma unroll
                for (int mt = 0; mt < 4; mt++) {
                    int rl = warp_m * 64 + mt * 16 + (lane & 15);
                    uint32_t a = sbase + (uint32_t)(rl * ROWB + (ks * 2 + cb) * 16);
                    ldsm_x4(af[mt], 1 * BUFB + a);
                }
                #pragma unroll
                for (int mt = 0; mt < 4; mt++)
                    #pragma unroll
                    for (int nt = 0; nt < 4; nt++)
                        mma16816(acc[mt][nt], af[mt], bhf[nt]);
            }
        }
        __syncthreads();
    }

    // ---- epilogue: relu + fp32 repr + bf16 hi/lo self cols for next layer ----
    #pragma unroll
    for (int mt = 0; mt < 4; mt++) {
        int row = row0 + warp_m * 64 + mt * 16 + (lane >> 2);
        #pragma unroll
        for (int nt = 0; nt < 4; nt++) {
            int col = warp_n * 32 + nt * 8 + (lane & 3) * 2;
            #pragma unroll
            for (int half = 0; half < 2; half++) {
                int rr = row + half * 8;
                float ox = fmaxf(acc[mt][nt][half * 2 + 0], 0.f);
                float oy = fmaxf(acc[mt][nt][half * 2 + 1], 0.f);
                *(float2*)(out + (size_t)rr * Hh + col) = make_float2(ox, oy);
                __nv_bfloat16 h0 = __float2bfloat16(ox);
                __nv_bfloat16 h1 = __float2bfloat16(oy);
                __nv_bfloat16 l0 = __float2bfloat16(ox - __bfloat162float(h0));
                __nv_bfloat16 l1 = __float2bfloat16(oy - __bfloat162float(h1));
                uint32_t uhi = (uint32_t)__bfloat16_as_ushort(h0) | ((uint32_t)__bfloat16_as_ushort(h1) << 16);
                uint32_t ulo = (uint32_t)__bfloat16_as_ushort(l0) | ((uint32_t)__bfloat16_as_ushort(l1) << 16);
                size_t so = (size_t)rr * KK + 1024 + col;
                *(uint32_t*)(g_Ahi + so) = uhi;
                *(uint32_t*)(g_Alo + so) = ulo;
            }
        }
    }
}

// ---------------------------------------------------------------------------
// Mean pooling: stage 1 partial sums over 8 node chunks; stage 2 combine.
// ---------------------------------------------------------------------------
__global__ void pool_part_kernel() {
    int bl = blockIdx.x;            // b*Ll + l
    int ck = blockIdx.y;            // 0..7
    int b = bl / Ll, l = bl % Ll, i = threadIdx.x;
    int n0 = ck * (NPG / 8);
    const float* p = g_repr + (size_t)l * Nn * Hh + (size_t)(b * NPG + n0) * Hh + i;
    float s = 0.f;
    for (int n = 0; n < NPG / 8; n++) s += p[(size_t)n * Hh];
    g_pool_part[((bl) * 8 + ck) * Hh + i] = s;
}
__global__ void pool_combine_kernel() {
    int bl = blockIdx.x, i = threadIdx.x;
    float s = 0.f;
    #pragma unroll
    for (int ck = 0; ck < 8; ck++) s += g_pool_part[(bl * 8 + ck) * Hh + i];
    g_mean_buf[bl * Hh + i] = s * (1.0f / NPG);
}

// ---------------------------------------------------------------------------
// Fused final head: one block per batch element, 128 threads.
// ---------------------------------------------------------------------------
__global__ void final_kernel(const float* __restrict__ rel_table,
                             const float* __restrict__ Zn,
                             const float* __restrict__ proj_W,
                             const float* __restrict__ proj_b,
                             const float* __restrict__ fc_W,
                             const float* __restrict__ fc_b,
                             const float* __restrict__ rep_seq,
                             const int* __restrict__ head_ids,
                             const int* __restrict__ tail_ids,
                             const int* __restrict__ rel_labels,
                             float* __restrict__ out)
{
    int b = blockIdx.x, i = threadIdx.x;
    __shared__ float sh_head[Ll * Hh], sh_tail[Ll * Hh], sh_gm[Ll * Hh];
    __shared__ float sh_gout[Hh], sh_hout[Hh], sh_tout[Hh];
    __shared__ float sh_e1[Kk], sh_e2[Kk];
    __shared__ float red[Hh];

    int head = head_ids[b], tail = tail_ids[b], rl = rel_labels[b];

    for (int j = i; j < Ll * Hh; j += Hh) {
        int l = j >> 7, c = j & 127;
        sh_head[j] = g_repr[(size_t)l * Nn * Hh + (size_t)head * Hh + c];
        sh_tail[j] = g_repr[(size_t)l * Nn * Hh + (size_t)tail * Hh + c];
        sh_gm[j]   = g_mean_buf[(b * Ll + l) * Hh + c];
    }
    __syncthreads();

    float bias = proj_b[i];
    float ag = bias, ah = bias, at = bias;
    for (int j = 0; j < Ll * Hh; j++) {
        float w = proj_W[j * Hh + i];
        ag = fmaf(sh_gm[j],   w, ag);
        ah = fmaf(sh_head[j], w, ah);
        at = fmaf(sh_tail[j], w, at);
    }
    sh_gout[i] = (ag >= 0.f) ? ag : 0.01f * ag;
    sh_hout[i] = ah;
    sh_tout[i] = at;
    __syncthreads();

    float lg1 = 0.f, lg2 = 0.f;
    if (i < Kk) {
        const float* z = Zn + (size_t)i * Hh;
        for (int c = 0; c < Hh; c++) {
            lg1 = fmaf(sh_hout[c], z[c], lg1);
            lg2 = fmaf(sh_tout[c], z[c], lg2);
        }
        sh_e1[i] = lg1; sh_e2[i] = lg2;
    }
    __syncthreads();
    float m1 = -1e30f, m2 = -1e30f;
    for (int k = 0; k < Kk; k++) {
        m1 = fmaxf(m1, sh_e1[k]);
        m2 = fmaxf(m2, sh_e2[k]);
    }
    __syncthreads();
    if (i < Kk) { sh_e1[i] = expf(lg1 - m1); sh_e2[i] = expf(lg2 - m2); }
    __syncthreads();
    float sum1 = 0.f, sum2 = 0.f;
    for (int k = 0; k < Kk; k++) { sum1 += sh_e1[k]; sum2 += sh_e2[k]; }
    float a1 = 0.f, a2 = 0.f;
    for (int k = 0; k < Kk; k++) {
        float zi = Zn[(size_t)k * Hh + i];
        a1 = fmaf(sh_e1[k], zi, a1);
        a2 = fmaf(sh_e2[k], zi, a2);
    }
    a1 /= sum1; a2 /= sum2;
    float sview = (1.f / (1.f + expf(-a1))) * (1.f / (1.f + expf(-a2)));

    float relv = rel_table[(size_t)rl * Hh + i];
    float v0 = sh_gout[i];
    float v1 = rep_seq[(size_t)b * Hh + i];
    float v2 = sview;

    float d[3];
    float parts[3] = {relv * v0, relv * v1, relv * v2};
    #pragma unroll
    for (int v = 0; v < 3; v++) {
        red[i] = parts[v];
        __syncthreads();
        for (int s = 64; s > 0; s >>= 1) {
            if (i < s) red[i] += red[i + s];
            __syncthreads();
        }
        d[v] = red[0];
        __syncthreads();
    }
    float dm = fmaxf(d[0], fmaxf(d[1], d[2]));
    float e0 = expf(d[0] - dm), e1 = expf(d[1] - dm), e2 = expf(d[2] - dm);
    float es = e0 + e1 + e2;
    float vag = (e0 * v0 + e1 * v1 + e2 * v2) / es;

    float part = 0.f;
    #pragma unroll
    for (int l = 0; l < Ll; l++) {
        part = fmaf(sh_head[l * Hh + i], fc_W[l * Hh + i], part);
        part = fmaf(sh_tail[l * Hh + i], fc_W[Ll * Hh + l * Hh + i], part);
    }
    part = fmaf(relv, fc_W[2 * Ll * Hh + i], part);
    part = fmaf(vag,  fc_W[2 * Ll * Hh + Hh + i], part);
    red[i] = part;
    __syncthreads();
    for (int s = 64; s > 0; s >>= 1) {
        if (i < s) red[i] += red[i + s];
        __syncthreads();
    }
    if (i == 0) out[b] = red[0] + fc_b[0];
}

// ---------------------------------------------------------------------------
extern "C" void kernel_launch(void* const* d_in, const int* in_sizes, int n_in,
                              void* d_out, int out_size) {
    const float* x         = (const float*)d_in[0];
    const float* W_rel     = (const float*)d_in[1];
    const float* W_self    = (const float*)d_in[2];
    const float* rel_table = (const float*)d_in[3];
    const float* Zn        = (const float*)d_in[4];
    const float* proj_W    = (const float*)d_in[5];
    const float* proj_b    = (const float*)d_in[6];
    const float* fc_W      = (const float*)d_in[7];
    const float* fc_b      = (const float*)d_in[8];
    const float* rep_seq   = (const float*)d_in[9];
    const int*   src       = (const int*)d_in[10];
    const int*   dst       = (const int*)d_in[11];
    const int*   etype     = (const int*)d_in[12];
    const int*   head_ids  = (const int*)d_in[14];
    const int*   tail_ids  = (const int*)d_in[15];
    const int*   rel_labels= (const int*)d_in[16];
    float* out = (float*)d_out;

    float* repr_base;
    cudaGetSymbolAddress((void**)&repr_base, g_repr);
    __nv_bfloat16* whi_base;
    __nv_bfloat16* wlo_base;
    cudaGetSymbolAddress((void**)&whi_base, g_Whi);
    cudaGetSymbolAddress((void**)&wlo_base, g_Wlo);

    cudaFuncSetAttribute(rgcn_mma_gemm_kernel,
                         cudaFuncAttributeMaxDynamicSharedMemorySize, SM_TOTAL);

    // one-time per launch: weights, x self-cols, CSR
    conv_w_kernel<<<(Ll * Hh * KK + 255) / 256, 256>>>(W_rel, W_self);
    xsplit_kernel<<<(Nn * Hh / 4 + 255) / 256, 256>>>(x);
    zero_cnt_kernel<<<NBINS / 256, 256>>>();
    count_kernel<<<(Ee + 255) / 256, 256>>>(dst);
    scan_kernel<<<1, 1024>>>();
    fill_kernel<<<(Ee + 255) / 256, 256>>>(src, dst, etype);

    const int gemm_blocks = Nn / 128;           // 250
    for (int l = 0; l < Ll; l++) {
        const float* h_in = (l == 0) ? x : (repr_base + (size_t)(l - 1) * Nn * Hh);
        float* h_out = repr_base + (size_t)l * Nn * Hh;
        gather_kernel<<<(Nn * 32) / 256, 256>>>(h_in);
        rgcn_mma_gemm_kernel<<<gemm_blocks, 256, SM_TOTAL>>>(
            whi_base + (size_t)l * Hh * KK,
            wlo_base + (size_t)l * Hh * KK,
            h_out);
    }
    dim3 pool_grid(BSz * Ll, 8);
    pool_part_kernel<<<pool_grid, Hh>>>();
    pool_combine_kernel<<<BSz * Ll, Hh>>>();
    final_kernel<<<BSz, Hh>>>(rel_table, Zn, proj_W, proj_b, fc_W, fc_b,
                              rep_seq, head_ids, tail_ids, rel_labels, out);
}